// round 1
// baseline (speedup 1.0000x reference)
#include <cuda_runtime.h>

#define TSTEPS 512
#define BSZ    256
#define DIN    128
#define HID    256
#define NPROTO 128
#define DHTOT  384          // DIN + HID
#define NB     4            // batches per CTA
#define NTHR   256

// Preprocessed weight layouts (device scratch — no allocation).
__device__ float4 g_Wpack[NPROTO][HID];          // [p][h] = {wf, wi, wg, wo}
__device__ float4 g_protoPack[DHTOT/4][NPROTO];  // [q][p] = proto[p][4q..4q+3]
__device__ float  g_pn2[NPROTO];                 // ||proto[p]||^2

typedef unsigned long long u64;

__device__ __forceinline__ u64 pk2(float lo, float hi){
    u64 r; asm("mov.b64 %0, {%1,%2};" : "=l"(r) : "f"(lo), "f"(hi)); return r;
}
__device__ __forceinline__ void upk2(u64 v, float& lo, float& hi){
    asm("mov.b64 {%0,%1}, %2;" : "=f"(lo), "=f"(hi) : "l"(v));
}
__device__ __forceinline__ u64 ffma2(u64 a, u64 b, u64 c){
    u64 d; asm("fma.rn.f32x2 %0, %1, %2, %3;" : "=l"(d) : "l"(a), "l"(b), "l"(c)); return d;
}
__device__ __forceinline__ float sigmf(float x){
    return __fdividef(1.f, 1.f + __expf(-x));
}
__device__ __forceinline__ float tanhf_(float x){
    // 1 - 2/(e^{2x}+1): no cancellation blowup, saturates correctly at +/-inf
    return 1.f - __fdividef(2.f, __expf(2.f*x) + 1.f);
}

__global__ void pack_kernel(const float* __restrict__ proto,
                            const float* __restrict__ Wf, const float* __restrict__ Wi,
                            const float* __restrict__ Wg, const float* __restrict__ Wo){
    int idx = blockIdx.x * blockDim.x + threadIdx.x;
    if (idx < HID*NPROTO){
        int h = idx >> 7, pp = idx & (NPROTO-1);
        g_Wpack[pp][h] = make_float4(Wf[idx], Wi[idx], Wg[idx], Wo[idx]);
    }
    if (idx < (DHTOT/4)*NPROTO){
        int q = idx >> 7, pp = idx & (NPROTO-1);
        const float* pr = proto + pp*DHTOT + 4*q;
        g_protoPack[q][pp] = make_float4(pr[0], pr[1], pr[2], pr[3]);
    }
    if (idx < NPROTO){
        float s = 0.f;
        for (int d = 0; d < DHTOT; ++d){ float v = proto[idx*DHTOT + d]; s = fmaf(v, v, s); }
        g_pn2[idx] = s;
    }
}

__global__ __launch_bounds__(NTHR, 1)
void qlstm_kernel(const float* __restrict__ x,
                  const float* __restrict__ bf, const float* __restrict__ bi,
                  const float* __restrict__ bg, const float* __restrict__ bo,
                  float* __restrict__ out){
    __shared__ float4 s_comb[DHTOT];           // [d] -> components = 4 batches (x | hx)
    __shared__ float2 s_kdup[NPROTO][NB];      // {k,k} duplicated for packed FMA
    __shared__ float4 s_part[2][NPROTO];       // dot partials (d-half, p) -> 4 batches
    __shared__ float  s_cn2[NB];

    const int tid = threadIdx.x;
    const int b0  = blockIdx.x * NB;
    const int p   = tid & (NPROTO-1);
    const int dh  = tid >> 7;                  // which d-half (0: d<192, 1: d>=192)

    // init hx = 0 (comb upper part), cx = 0
    s_comb[DIN + tid] = make_float4(0.f, 0.f, 0.f, 0.f);
    float cx0 = 0.f, cx1 = 0.f, cx2 = 0.f, cx3 = 0.f;

    const u64 bFI = pk2(bf[tid], bi[tid]);
    const u64 bGO = pk2(bg[tid], bo[tid]);
    const float pn2v = g_pn2[p];

    const ulonglong2* __restrict__ wcol = reinterpret_cast<const ulonglong2*>(g_Wpack) + tid;
    const float4*     __restrict__ pcol = &g_protoPack[dh*48][p];
    const ulonglong2* comb2 = reinterpret_cast<const ulonglong2*>(s_comb) + dh*192;
    float*            combf = reinterpret_cast<float*>(s_comb);
    const u64*        kflat = reinterpret_cast<const u64*>(s_kdup);

    for (int t = 0; t < TSTEPS; ++t){
        // ---- phase 1: load x_t into comb[0..DIN) (hx already in comb[DIN..)) ----
        const float* xb = x + ((size_t)t*BSZ + b0)*DIN;
        #pragma unroll
        for (int it = 0; it < 2; ++it){
            int idx = tid + it*NTHR;            // 0..511 -> (b, d)
            int b = idx >> 7, d = idx & (DIN-1);
            combf[d*4 + b] = xb[b*DIN + d];
        }
        __syncthreads();                        // comb fully visible

        // ---- cn2 = ||combined_b||^2 (warp 0, overlapped with dot phase start) ----
        if (tid < 32){
            float ax=0.f, ay=0.f, az=0.f, aw=0.f;
            #pragma unroll
            for (int j = 0; j < 12; ++j){
                float4 c = s_comb[tid + 32*j];
                ax = fmaf(c.x,c.x,ax); ay = fmaf(c.y,c.y,ay);
                az = fmaf(c.z,c.z,az); aw = fmaf(c.w,c.w,aw);
            }
            #pragma unroll
            for (int off = 16; off; off >>= 1){
                ax += __shfl_xor_sync(0xffffffffu, ax, off);
                ay += __shfl_xor_sync(0xffffffffu, ay, off);
                az += __shfl_xor_sync(0xffffffffu, az, off);
                aw += __shfl_xor_sync(0xffffffffu, aw, off);
            }
            if (tid == 0){ s_cn2[0]=ax; s_cn2[1]=ay; s_cn2[2]=az; s_cn2[3]=aw; }
        }

        // ---- phase 2: dot(c_b, proto_p) partials over this thread's d-half ----
        u64 a01 = 0ull, a23 = 0ull;             // packed {b0,b1}, {b2,b3}
        #pragma unroll 4
        for (int q = 0; q < 48; ++q){
            float4 pv = pcol[q*NPROTO];         // coalesced over p (4 wf / LDG.128)
            ulonglong2 c0 = comb2[4*q+0];
            ulonglong2 c1 = comb2[4*q+1];
            ulonglong2 c2 = comb2[4*q+2];
            ulonglong2 c3 = comb2[4*q+3];
            u64 v0 = pk2(pv.x, pv.x), v1 = pk2(pv.y, pv.y);
            u64 v2 = pk2(pv.z, pv.z), v3 = pk2(pv.w, pv.w);
            a01 = ffma2(c0.x, v0, a01); a23 = ffma2(c0.y, v0, a23);
            a01 = ffma2(c1.x, v1, a01); a23 = ffma2(c1.y, v1, a23);
            a01 = ffma2(c2.x, v2, a01); a23 = ffma2(c2.y, v2, a23);
            a01 = ffma2(c3.x, v3, a01); a23 = ffma2(c3.y, v3, a23);
        }
        {
            float d0, d1, d2v, d3;
            upk2(a01, d0, d1); upk2(a23, d2v, d3);
            s_part[dh][p] = make_float4(d0, d1, d2v, d3);
        }
        __syncthreads();                        // partials + cn2 ready

        // ---- phase 3: finish k = exp(-(cn2 + pn2 - 2 dot)), duplicated store ----
        if (tid < NPROTO){
            float4 u = s_part[0][tid];
            float4 v = s_part[1][tid];
            float k0 = __expf(2.f*(u.x+v.x) - pn2v - s_cn2[0]);
            float k1 = __expf(2.f*(u.y+v.y) - pn2v - s_cn2[1]);
            float k2 = __expf(2.f*(u.z+v.z) - pn2v - s_cn2[2]);
            float k3 = __expf(2.f*(u.w+v.w) - pn2v - s_cn2[3]);
            s_kdup[tid][0] = make_float2(k0, k0);
            s_kdup[tid][1] = make_float2(k1, k1);
            s_kdup[tid][2] = make_float2(k2, k2);
            s_kdup[tid][3] = make_float2(k3, k3);
        }
        __syncthreads();                        // k ready

        // ---- phase 4: gate GEMM, thread owns h = tid, all 4 gates x 4 batches ----
        u64 aFI0=bFI, aFI1=bFI, aFI2=bFI, aFI3=bFI;
        u64 aGO0=bGO, aGO1=bGO, aGO2=bGO, aGO3=bGO;
        #pragma unroll 8
        for (int pp = 0; pp < NPROTO; ++pp){
            ulonglong2 w = wcol[pp*HID];        // {wf,wi},{wg,wo} — coalesced over h
            u64 k0 = kflat[pp*4+0], k1 = kflat[pp*4+1];
            u64 k2 = kflat[pp*4+2], k3 = kflat[pp*4+3];
            aFI0 = ffma2(w.x, k0, aFI0); aGO0 = ffma2(w.y, k0, aGO0);
            aFI1 = ffma2(w.x, k1, aFI1); aGO1 = ffma2(w.y, k1, aGO1);
            aFI2 = ffma2(w.x, k2, aFI2); aGO2 = ffma2(w.y, k2, aGO2);
            aFI3 = ffma2(w.x, k3, aFI3); aGO3 = ffma2(w.y, k3, aGO3);
        }

        // ---- phase 5: LSTM cell update + output write ----
        float* orow = out + ((size_t)t*BSZ + b0)*HID + tid;
        {
            float fp, ip, gp, op;
            upk2(aFI0, fp, ip); upk2(aGO0, gp, op);
            float fv = sigmf(fp), iv = sigmf(ip), gv = tanhf_(gp), ov = sigmf(op);
            cx0 = fv*cx0 + iv*gv;
            float hv = ov * tanhf_(cx0);
            combf[(DIN+tid)*4 + 0] = hv;
            orow[0*HID] = hv;
        }
        {
            float fp, ip, gp, op;
            upk2(aFI1, fp, ip); upk2(aGO1, gp, op);
            float fv = sigmf(fp), iv = sigmf(ip), gv = tanhf_(gp), ov = sigmf(op);
            cx1 = fv*cx1 + iv*gv;
            float hv = ov * tanhf_(cx1);
            combf[(DIN+tid)*4 + 1] = hv;
            orow[1*HID] = hv;
        }
        {
            float fp, ip, gp, op;
            upk2(aFI2, fp, ip); upk2(aGO2, gp, op);
            float fv = sigmf(fp), iv = sigmf(ip), gv = tanhf_(gp), ov = sigmf(op);
            cx2 = fv*cx2 + iv*gv;
            float hv = ov * tanhf_(cx2);
            combf[(DIN+tid)*4 + 2] = hv;
            orow[2*HID] = hv;
        }
        {
            float fp, ip, gp, op;
            upk2(aFI3, fp, ip); upk2(aGO3, gp, op);
            float fv = sigmf(fp), iv = sigmf(ip), gv = tanhf_(gp), ov = sigmf(op);
            cx3 = fv*cx3 + iv*gv;
            float hv = ov * tanhf_(cx3);
            combf[(DIN+tid)*4 + 3] = hv;
            orow[3*HID] = hv;
        }
        // No trailing sync needed: next iter's sync1 orders comb-lo rewrite,
        // and comb-hi/k rewrites are each two syncs away from their readers.
    }

    // ---- finals: hx then cx appended after outputs ----
    const size_t TBH = (size_t)TSTEPS * BSZ * HID;
    const size_t BH  = (size_t)BSZ * HID;
    float4 hf = s_comb[DIN + tid];   // own writes — no sync needed
    out[TBH + (size_t)(b0+0)*HID + tid] = hf.x;
    out[TBH + (size_t)(b0+1)*HID + tid] = hf.y;
    out[TBH + (size_t)(b0+2)*HID + tid] = hf.z;
    out[TBH + (size_t)(b0+3)*HID + tid] = hf.w;
    out[TBH + BH + (size_t)(b0+0)*HID + tid] = cx0;
    out[TBH + BH + (size_t)(b0+1)*HID + tid] = cx1;
    out[TBH + BH + (size_t)(b0+2)*HID + tid] = cx2;
    out[TBH + BH + (size_t)(b0+3)*HID + tid] = cx3;
}

extern "C" void kernel_launch(void* const* d_in, const int* in_sizes, int n_in,
                              void* d_out, int out_size){
    (void)in_sizes; (void)n_in; (void)out_size;
    const float* inputs = (const float*)d_in[0];
    const float* proto  = (const float*)d_in[1];
    const float* Wf     = (const float*)d_in[2];
    const float* bf     = (const float*)d_in[3];
    const float* Wi     = (const float*)d_in[4];
    const float* bi     = (const float*)d_in[5];
    const float* Wg     = (const float*)d_in[6];
    const float* bg     = (const float*)d_in[7];
    const float* Wo     = (const float*)d_in[8];
    const float* bo     = (const float*)d_in[9];
    float* out = (float*)d_out;

    pack_kernel<<<(HID*NPROTO + NTHR - 1)/NTHR, NTHR>>>(proto, Wf, Wi, Wg, Wo);
    qlstm_kernel<<<BSZ/NB, NTHR>>>(inputs, bf, bi, bg, bo, out);
}

// round 2
// speedup vs baseline: 1.4971x; 1.4971x over previous
#include <cuda_runtime.h>
#include <cstdint>

#define TSTEPS 512
#define BSZ    256
#define DIN    128
#define HID    256
#define NPROTO 128
#define DHTOT  384
#define NB     8            // batches per cluster
#define CSZ    4            // CTAs per cluster
#define NTHR   256
#define NCTA   (BSZ / NB * CSZ)   // 128

// Preprocessed weight layouts (device scratch — no allocation).
__device__ float4 g_Wpack[NPROTO][HID];          // [p][h] = {wf, wi, wg, wo}
__device__ float4 g_protoPack[DHTOT/4][NPROTO];  // [q][p] = proto[p][4q..4q+3]
__device__ float  g_pn2[NPROTO];

typedef unsigned long long u64;

// ---------------- smem layout (dynamic) ----------------
// WQ  : [128 p][64 h_local] float4          131072
// COMB: [4 pair][384 d] u64 ({b_even,b_odd}) 12288
// KD  : [128 p][8 b] u64 ({k,k})              8192
// PG  : [4 pc][8 b][2 fi][64 h] u64          32768   (PD aliases first 8KB)
// PD  : [8 dc][4 pair][32 pl] u64             8192   (alias @ PG)
// CN  : [4 pair] u64                            32
#define WQ_OFF    0
#define COMB_OFF  131072
#define KD_OFF    143360
#define PG_OFF    151552
#define PD_OFF    151552
#define CN_OFF    184320
#define SMEM_TOTAL 184384

__device__ __forceinline__ u64 pk2(float lo, float hi){
    u64 r; asm("mov.b64 %0, {%1,%2};" : "=l"(r) : "f"(lo), "f"(hi)); return r;
}
__device__ __forceinline__ void upk2(u64 v, float& lo, float& hi){
    asm("mov.b64 {%0,%1}, %2;" : "=f"(lo), "=f"(hi) : "l"(v));
}
__device__ __forceinline__ u64 ffma2(u64 a, u64 b, u64 c){
    u64 d; asm("fma.rn.f32x2 %0, %1, %2, %3;" : "=l"(d) : "l"(a), "l"(b), "l"(c)); return d;
}
__device__ __forceinline__ u64 add2(u64 a, u64 b){
    u64 d; asm("add.rn.f32x2 %0, %1, %2;" : "=l"(d) : "l"(a), "l"(b)); return d;
}
__device__ __forceinline__ float sigmf(float x){
    return __fdividef(1.f, 1.f + __expf(-x));
}
__device__ __forceinline__ float tanhf_(float x){
    return 1.f - __fdividef(2.f, __expf(2.f*x) + 1.f);
}
__device__ __forceinline__ uint32_t smem_u32(const void* p){
    uint32_t a;
    asm("{ .reg .u64 t; cvta.to.shared.u64 t, %1; cvt.u32.u64 %0, t; }" : "=r"(a) : "l"(p));
    return a;
}
__device__ __forceinline__ uint32_t ctarank(){
    uint32_t r; asm("mov.u32 %0, %%cluster_ctarank;" : "=r"(r)); return r;
}
__device__ __forceinline__ uint32_t mapa_u32(uint32_t local, uint32_t rank){
    uint32_t r; asm("mapa.shared::cluster.u32 %0, %1, %2;" : "=r"(r) : "r"(local), "r"(rank));
    return r;
}
__device__ __forceinline__ void st_cl64(uint32_t addr, u64 v){
    asm volatile("st.shared::cluster.b64 [%0], %1;" :: "r"(addr), "l"(v) : "memory");
}
__device__ __forceinline__ void cluster_bar(){
    asm volatile("barrier.cluster.arrive.aligned;" ::: "memory");   // release
    asm volatile("barrier.cluster.wait.aligned;"   ::: "memory");   // acquire
}

__global__ void pack_kernel(const float* __restrict__ proto,
                            const float* __restrict__ Wf, const float* __restrict__ Wi,
                            const float* __restrict__ Wg, const float* __restrict__ Wo){
    int idx = blockIdx.x * blockDim.x + threadIdx.x;
    if (idx < HID*NPROTO){
        int h = idx >> 7, pp = idx & (NPROTO-1);
        g_Wpack[pp][h] = make_float4(Wf[idx], Wi[idx], Wg[idx], Wo[idx]);
    }
    if (idx < (DHTOT/4)*NPROTO){
        int q = idx >> 7, pp = idx & (NPROTO-1);
        const float* pr = proto + pp*DHTOT + 4*q;
        g_protoPack[q][pp] = make_float4(pr[0], pr[1], pr[2], pr[3]);
    }
    if (idx < NPROTO){
        float s = 0.f;
        for (int d = 0; d < DHTOT; ++d){ float v = proto[idx*DHTOT + d]; s = fmaf(v, v, s); }
        g_pn2[idx] = s;
    }
}

extern __shared__ char sm[];

__global__ void __cluster_dims__(CSZ,1,1) __launch_bounds__(NTHR, 1)
qlstm_kernel(const float* __restrict__ x,
             const float* __restrict__ bf, const float* __restrict__ bi,
             const float* __restrict__ bg, const float* __restrict__ bo,
             float* __restrict__ out){
    const int tid  = threadIdx.x;
    const uint32_t rank = ctarank();
    const int bbase = (blockIdx.x >> 2) * NB;     // cluster's batch base
    const uint32_t base = smem_u32(sm);

    float4*     WQ    = reinterpret_cast<float4*>(sm + WQ_OFF);     // [p][h_local]
    u64*        COMB  = reinterpret_cast<u64*>(sm + COMB_OFF);      // [pair*384 + d]
    float*      COMBF = reinterpret_cast<float*>(sm + COMB_OFF);
    u64*        KD    = reinterpret_cast<u64*>(sm + KD_OFF);        // [p*8 + b]
    const ulonglong2* KD2 = reinterpret_cast<const ulonglong2*>(sm + KD_OFF); // [p*4+i]
    u64*        PG    = reinterpret_cast<u64*>(sm + PG_OFF);        // [((pc*8+b)*2+fi)*64+h]
    u64*        PD    = reinterpret_cast<u64*>(sm + PD_OFF);        // [(dc*4+pr)*32+pl]
    u64*        CN    = reinterpret_cast<u64*>(sm + CN_OFF);        // [pair]

    // ---- preamble: fill weight quarter into smem ----
    {
        const float4* src = &g_Wpack[0][rank*64];
        #pragma unroll
        for (int i = 0; i < (NPROTO*64)/NTHR; ++i){
            int idx = tid + i*NTHR;               // idx -> p*64 + hl
            int p  = idx >> 6, hl = idx & 63;
            WQ[idx] = src[p*HID + hl];
        }
    }
    // zero hx region of comb
    #pragma unroll
    for (int i = 0; i < (CSZ*(DHTOT-DIN))/NTHR*1; ++i){
        int idx = tid + i*NTHR;                   // 0..1023
        COMB[(idx >> 8)*DHTOT + DIN + (idx & 255)] = 0ull;
    }

    // per-thread constants
    const int hL    = tid & 63;                   // gate/reduce h_local
    const int pcG   = tid >> 6;                   // gate pchunk / reduce pair
    const int hglob = rank*64 + hL;
    const u64 bFI   = pk2(bf[hglob], bi[hglob]);
    const u64 bGO   = pk2(bg[hglob], bo[hglob]);

    const int plD = tid & 31;                     // dist p_local
    const int dcD = tid >> 5;                     // dist d-chunk (0..7)
    const float pn2v = g_pn2[rank*32 + plD];      // used when tid<128

    // hoisted DSMEM addresses
    uint32_t kAddr[CSZ], hvAddr[CSZ];
    {
        uint32_t koff = base + KD_OFF + (uint32_t)(((rank*32 + plD)*8 + 2*(tid>>5))*8);
        uint32_t hoff = base + COMB_OFF + (uint32_t)((pcG*DHTOT + DIN + hglob)*8);
        #pragma unroll
        for (uint32_t r = 0; r < CSZ; ++r){
            kAddr[r]  = mapa_u32(koff, r);
            hvAddr[r] = mapa_u32(hoff, r);
        }
    }

    const float4* pcol = &g_protoPack[dcD*12][rank*32 + plD];

    float cx0 = 0.f, cx1 = 0.f;
    float hv0 = 0.f, hv1 = 0.f;

    __syncthreads();
    cluster_bar();                                // everyone initialized

    for (int t = 0; t < TSTEPS; ++t){
        // ---- phase 1: x fill (L1-bypassing loads) ----
        const float* xb = x + ((size_t)t*BSZ + bbase)*DIN;
        #pragma unroll
        for (int i = 0; i < (NB*DIN)/NTHR; ++i){
            int idx = tid + i*NTHR;               // (b,d)
            int b = idx >> 7, d = idx & (DIN-1);
            COMBF[(b >> 1)*DHTOT*2 + d*2 + (b & 1)] = __ldcg(&xb[idx]);
        }
        __syncthreads();                          // comb complete (hv via prior cluster bar)

        // ---- phase 2a: cn2 (warps 0-3, one batch-pair each) ----
        if ((tid >> 5) < 4){
            int pr = tid >> 5, lane = tid & 31;
            u64 a = 0ull;
            #pragma unroll
            for (int j = 0; j < 12; ++j){
                u64 c = COMB[pr*DHTOT + lane + 32*j];
                a = ffma2(c, c, a);
            }
            #pragma unroll
            for (int off = 16; off; off >>= 1)
                a = add2(a, __shfl_xor_sync(0xffffffffu, a, off));
            if (lane == 0) CN[pr] = a;
        }

        // ---- phase 2b: dist partials (thread = (pl, dc), 12 float4 rows) ----
        {
            u64 a0 = 0ull, a1 = 0ull, a2 = 0ull, a3 = 0ull;
            const int d0base = dcD*48;
            #pragma unroll 3
            for (int j = 0; j < 12; ++j){
                float4 pv = pcol[j*NPROTO];       // L1-resident proto slice
                int d0 = d0base + 4*j;
                u64 v0 = pk2(pv.x, pv.x), v1 = pk2(pv.y, pv.y);
                u64 v2 = pk2(pv.z, pv.z), v3 = pk2(pv.w, pv.w);
                #pragma unroll
                for (int pr = 0; pr < 4; ++pr){
                    const ulonglong2* c2 = reinterpret_cast<const ulonglong2*>(COMB + pr*DHTOT + d0);
                    ulonglong2 cA = c2[0];
                    ulonglong2 cB = c2[1];
                    u64 acc = (pr==0)?a0:(pr==1)?a1:(pr==2)?a2:a3;
                    acc = ffma2(cA.x, v0, acc);
                    acc = ffma2(cA.y, v1, acc);
                    acc = ffma2(cB.x, v2, acc);
                    acc = ffma2(cB.y, v3, acc);
                    if (pr==0) a0=acc; else if (pr==1) a1=acc; else if (pr==2) a2=acc; else a3=acc;
                }
            }
            PD[(dcD*4 + 0)*32 + plD] = a0;
            PD[(dcD*4 + 1)*32 + plD] = a1;
            PD[(dcD*4 + 2)*32 + plD] = a2;
            PD[(dcD*4 + 3)*32 + plD] = a3;
        }
        __syncthreads();                          // PD + CN ready

        // ---- phase 3: k finish + cluster broadcast (threads 0..127) ----
        if (tid < 128){
            int pl = tid & 31, pr = tid >> 5;
            u64 dot = PD[(0*4 + pr)*32 + pl];
            #pragma unroll
            for (int dc = 1; dc < 8; ++dc)
                dot = add2(dot, PD[(dc*4 + pr)*32 + pl]);
            float d0, d1; upk2(dot, d0, d1);
            float c0, c1; upk2(CN[pr], c0, c1);
            float k0 = __expf(2.f*d0 - pn2v - c0);
            float k1 = __expf(2.f*d1 - pn2v - c1);
            u64 kk0 = pk2(k0, k0), kk1 = pk2(k1, k1);
            #pragma unroll
            for (int r = 0; r < CSZ; ++r){
                st_cl64(kAddr[r],     kk0);
                st_cl64(kAddr[r] + 8, kk1);
            }
        }
        cluster_bar();                            // A: all k visible everywhere

        // ---- phase 4: gate partial GEMM (thread = (hL, pcG), 32 p's) ----
        {
            u64 F0=0,F1=0,F2=0,F3=0,F4=0,F5=0,F6=0,F7=0;
            u64 G0=0,G1=0,G2=0,G3=0,G4=0,G5=0,G6=0,G7=0;
            const ulonglong2* wp = reinterpret_cast<const ulonglong2*>(WQ) + (pcG*32)*64 + hL;
            const ulonglong2* kp = KD2 + (pcG*32)*4;
            #pragma unroll 2
            for (int j = 0; j < 32; ++j){
                ulonglong2 w  = wp[j*64];
                ulonglong2 kA = kp[j*4 + 0];
                ulonglong2 kB = kp[j*4 + 1];
                ulonglong2 kC = kp[j*4 + 2];
                ulonglong2 kD_ = kp[j*4 + 3];
                F0 = ffma2(w.x, kA.x, F0);  G0 = ffma2(w.y, kA.x, G0);
                F1 = ffma2(w.x, kA.y, F1);  G1 = ffma2(w.y, kA.y, G1);
                F2 = ffma2(w.x, kB.x, F2);  G2 = ffma2(w.y, kB.x, G2);
                F3 = ffma2(w.x, kB.y, F3);  G3 = ffma2(w.y, kB.y, G3);
                F4 = ffma2(w.x, kC.x, F4);  G4 = ffma2(w.y, kC.x, G4);
                F5 = ffma2(w.x, kC.y, F5);  G5 = ffma2(w.y, kC.y, G5);
                F6 = ffma2(w.x, kD_.x, F6); G6 = ffma2(w.y, kD_.x, G6);
                F7 = ffma2(w.x, kD_.y, F7); G7 = ffma2(w.y, kD_.y, G7);
            }
            u64* pg = PG + (pcG*8)*2*64 + hL;
            pg[(0*2+0)*64] = F0; pg[(0*2+1)*64] = G0;
            pg[(1*2+0)*64] = F1; pg[(1*2+1)*64] = G1;
            pg[(2*2+0)*64] = F2; pg[(2*2+1)*64] = G2;
            pg[(3*2+0)*64] = F3; pg[(3*2+1)*64] = G3;
            pg[(4*2+0)*64] = F4; pg[(4*2+1)*64] = G4;
            pg[(5*2+0)*64] = F5; pg[(5*2+1)*64] = G5;
            pg[(6*2+0)*64] = F6; pg[(6*2+1)*64] = G6;
            pg[(7*2+0)*64] = F7; pg[(7*2+1)*64] = G7;
        }
        __syncthreads();                          // PG ready

        // ---- phase 5: reduce over pchunks + activations + cx/hv ----
        {
            const int b0 = 2*pcG, b1 = 2*pcG + 1;
            u64 Fa = bFI, Ga = bGO, Fb = bFI, Gb = bGO;
            #pragma unroll
            for (int c = 0; c < 4; ++c){
                const u64* pg = PG + (c*8)*2*64 + hL;
                Fa = add2(Fa, pg[(b0*2+0)*64]);
                Ga = add2(Ga, pg[(b0*2+1)*64]);
                Fb = add2(Fb, pg[(b1*2+0)*64]);
                Gb = add2(Gb, pg[(b1*2+1)*64]);
            }
            float fp, ip, gp, op;
            upk2(Fa, fp, ip); upk2(Ga, gp, op);
            {
                float fv = sigmf(fp), iv = sigmf(ip), gv = tanhf_(gp), ov = sigmf(op);
                cx0 = fv*cx0 + iv*gv;
                hv0 = ov * tanhf_(cx0);
            }
            upk2(Fb, fp, ip); upk2(Gb, gp, op);
            {
                float fv = sigmf(fp), iv = sigmf(ip), gv = tanhf_(gp), ov = sigmf(op);
                cx1 = fv*cx1 + iv*gv;
                hv1 = ov * tanhf_(cx1);
            }
            u64 hvp = pk2(hv0, hv1);
            #pragma unroll
            for (int r = 0; r < CSZ; ++r) st_cl64(hvAddr[r], hvp);

            float* orow = out + ((size_t)t*BSZ + bbase)*HID + hglob;
            orow[(size_t)b0*HID] = hv0;
            orow[(size_t)b1*HID] = hv1;
        }
        cluster_bar();                            // B: hv visible everywhere
    }

    // ---- finals: hx, cx after outputs ----
    {
        const size_t TBH = (size_t)TSTEPS * BSZ * HID;
        const size_t BH  = (size_t)BSZ * HID;
        const int b0 = bbase + 2*pcG, b1 = b0 + 1;
        out[TBH + (size_t)b0*HID + hglob] = hv0;
        out[TBH + (size_t)b1*HID + hglob] = hv1;
        out[TBH + BH + (size_t)b0*HID + hglob] = cx0;
        out[TBH + BH + (size_t)b1*HID + hglob] = cx1;
    }
}

extern "C" void kernel_launch(void* const* d_in, const int* in_sizes, int n_in,
                              void* d_out, int out_size){
    (void)in_sizes; (void)n_in; (void)out_size;
    const float* inputs = (const float*)d_in[0];
    const float* proto  = (const float*)d_in[1];
    const float* Wf     = (const float*)d_in[2];
    const float* bf     = (const float*)d_in[3];
    const float* Wi     = (const float*)d_in[4];
    const float* bi     = (const float*)d_in[5];
    const float* Wg     = (const float*)d_in[6];
    const float* bg     = (const float*)d_in[7];
    const float* Wo     = (const float*)d_in[8];
    const float* bo     = (const float*)d_in[9];
    float* out = (float*)d_out;

    cudaFuncSetAttribute(qlstm_kernel,
                         cudaFuncAttributeMaxDynamicSharedMemorySize, SMEM_TOTAL);

    pack_kernel<<<(HID*NPROTO + NTHR - 1)/NTHR, NTHR>>>(proto, Wf, Wi, Wg, Wo);
    qlstm_kernel<<<NCTA, NTHR, SMEM_TOTAL>>>(inputs, bf, bi, bg, bo, out);
}